// round 1
// baseline (speedup 1.0000x reference)
#include <cuda_runtime.h>

// ---------------- scratch (static device memory; no allocation) ----------------
__device__ float d_wtp[2048u * 6144u];        // wt permuted: [i][p*2048+o]
__device__ float d_wct[3u * 2048u * 2048u];   // wc transposed: [q][i][o]
__device__ float d_k1[200 * 6144];            // stage1 out: [n][p*2048+o]
__device__ float d_k2[200 * 6144];            // stage2 out: [n][p*2048+o]
__device__ float d_g [64 * 6144];             // fused feat reduction: [b][q*2048+c]
__device__ float d_part[32 * 64 * 200];       // split-K partials for stage3
__device__ float d_cls[64 * 200];             // cls_feat
__device__ float d_norms[264];                // 64 cls rnorms + 200 w_cls rnorms

static inline int cdiv(int a, int b) { return (a + b - 1) / b; }

__device__ __forceinline__ float wredsum(float v) {
#pragma unroll
    for (int o = 16; o > 0; o >>= 1) v += __shfl_xor_sync(0xffffffffu, v, o);
    return v;
}

// ---------------- P1: permute wt [i][o*3+p] -> wtp [i][p*2048+o] ----------------
__global__ void permute_wt_kernel(const float* __restrict__ wt, float* __restrict__ wtp) {
    __shared__ __align__(16) float s[6144];
    const int i = blockIdx.x;  // 2048 rows
    const float* src = wt + (size_t)i * 6144;
    for (int t = threadIdx.x; t < 1536; t += 256)
        reinterpret_cast<float4*>(s)[t] = reinterpret_cast<const float4*>(src)[t];
    __syncthreads();
    float* dst = d_wtp + (size_t)i * 6144;
    for (int m = threadIdx.x; m < 6144; m += 256) {
        int o = m & 2047, p = m >> 11;
        dst[m] = s[o * 3 + p];
    }
    (void)wtp;
}

// ---------------- P2: transpose wc [o][i*3+q] -> wct [q][i][o] ----------------
__global__ void permute_wc_kernel(const float* __restrict__ wc) {
    __shared__ float t3[3][32][33];
    const int o0 = blockIdx.x * 32;
    const int i0 = blockIdx.y * 32;
    // read 32 o-rows x 96 floats (i0*3 .. i0*3+96)
    for (int v = threadIdx.x; v < 768; v += 256) {
        int orow = v / 24;
        int col4 = v % 24;
        float4 val = *reinterpret_cast<const float4*>(
            wc + (size_t)(o0 + orow) * 6144 + i0 * 3 + col4 * 4);
        int f = col4 * 4;
        float e[4] = {val.x, val.y, val.z, val.w};
#pragma unroll
        for (int k = 0; k < 4; k++) {
            int ff = f + k;
            t3[ff % 3][ff / 3][orow] = e[k];
        }
    }
    __syncthreads();
    for (int v = threadIdx.x; v < 3 * 32 * 32; v += 256) {
        int q = v >> 10;
        int rem = v & 1023;
        int il = rem >> 5;
        int oc = rem & 31;
        d_wct[(size_t)q * 4194304u + (size_t)(i0 + il) * 2048 + o0 + oc] = t3[q][il][oc];
    }
}

// ---------------- G: g[b][p*2048+c] = sum_s w_sp[s]*feat[b,c,s+p-1] ----------------
__global__ void g_kernel(const float* __restrict__ feat, const float* __restrict__ w_sp) {
    __shared__ float ws[200];  // ws[0]=0, ws[1..196]=w_sp, ws[197]=0
    const int tid = threadIdx.x;
    if (tid < 198) {
        float v = 0.f;
        if (tid >= 1 && tid <= 196) v = w_sp[tid - 1];
        ws[tid] = v;
    }
    __syncthreads();
    const int w = blockIdx.x * 8 + (tid >> 5);  // global warp id, 131072 total
    const int lane = tid & 31;
    const int b = w >> 11;
    const int c = w & 2047;
    const float* x = feat + ((size_t)b * 2048 + c) * 196;
    float a0 = 0.f, a1 = 0.f, a2 = 0.f;
    for (int t = lane; t < 196; t += 32) {
        float xv = x[t];
        a0 = fmaf(xv, ws[t + 2], a0);  // p=0: w_sp[t+1]
        a1 = fmaf(xv, ws[t + 1], a1);  // p=1: w_sp[t]
        a2 = fmaf(xv, ws[t],     a2);  // p=2: w_sp[t-1]
    }
    a0 = wredsum(a0); a1 = wredsum(a1); a2 = wredsum(a2);
    if (lane == 0) {
        d_g[(size_t)b * 6144 + c]        = a0;
        d_g[(size_t)b * 6144 + 2048 + c] = a1;
        d_g[(size_t)b * 6144 + 4096 + c] = a2;
    }
}

// ---------------- GEMM64: 64x64 tile, BK=8, fp32, bias(col&2047)+relu ----------------
// stageB=0: C[n, col] = sum_i A[n,i]*B[i*ldb + col],          N=6144 (wtp path)
// stageB=1: conv taps:  C[n, p*2048+o] accumulated over (j,q) segments of K=2048
__global__ void __launch_bounds__(256)
gemm64(const float* __restrict__ A, int lda,
       const float* __restrict__ B, int ldb,
       float* __restrict__ C, int ldc,
       int M, int stageB, const float* __restrict__ bias)
{
    __shared__ __align__(16) float As[8][68];
    __shared__ __align__(16) float Bs[8][68];
    const int tid = threadIdx.x;
    const int brow = blockIdx.y * 64;
    const int bcol = blockIdx.x * 64;

    int nseg;
    int aoffs[3], boffs[3];
    if (stageB) {
        const int p = bcol >> 11;
        const int bl = bcol & 2047;
        int js[3], qs[3];
        if (p == 0)      { nseg = 2; js[0]=0; js[1]=1; js[2]=0; qs[0]=1; qs[1]=2; qs[2]=0; }
        else if (p == 1) { nseg = 3; js[0]=0; js[1]=1; js[2]=2; qs[0]=0; qs[1]=1; qs[2]=2; }
        else             { nseg = 2; js[0]=1; js[1]=2; js[2]=0; qs[0]=0; qs[1]=1; qs[2]=0; }
#pragma unroll
        for (int s = 0; s < 3; s++) {
            aoffs[s] = js[s] * 2048;
            boffs[s] = qs[s] * 4194304 + bl;
        }
    } else {
        nseg = 1;
        aoffs[0] = 0; boffs[0] = bcol;
        aoffs[1] = aoffs[2] = 0; boffs[1] = boffs[2] = 0;
    }

    float acc[4][4];
#pragma unroll
    for (int i = 0; i < 4; i++)
#pragma unroll
        for (int j = 0; j < 4; j++) acc[i][j] = 0.f;

    const int tx = tid & 15, ty = tid >> 4;
    const bool loadA = tid < 128;
    const int arow = (tid & 127) >> 1;
    const int akq  = (tid & 1) * 4;
    const int t2   = tid & 127;
    const int bkr  = t2 >> 4;
    const int bnq  = (t2 & 15) * 4;

    for (int s = 0; s < nseg; s++) {
        const float* Ab = A + aoffs[s];
        const float* Bb = B + boffs[s];
        for (int k0 = 0; k0 < 2048; k0 += 8) {
            if (loadA) {
                int r = brow + arow;
                float4 av = make_float4(0.f, 0.f, 0.f, 0.f);
                if (r < M) av = *reinterpret_cast<const float4*>(Ab + (size_t)r * lda + k0 + akq);
                As[akq + 0][arow] = av.x;
                As[akq + 1][arow] = av.y;
                As[akq + 2][arow] = av.z;
                As[akq + 3][arow] = av.w;
            } else {
                float4 bv = *reinterpret_cast<const float4*>(Bb + (size_t)(k0 + bkr) * ldb + bnq);
                *reinterpret_cast<float4*>(&Bs[bkr][bnq]) = bv;
            }
            __syncthreads();
#pragma unroll
            for (int k = 0; k < 8; k++) {
                float a[4], bb[4];
                *reinterpret_cast<float4*>(a)  = *reinterpret_cast<const float4*>(&As[k][ty * 4]);
                *reinterpret_cast<float4*>(bb) = *reinterpret_cast<const float4*>(&Bs[k][tx * 4]);
#pragma unroll
                for (int i = 0; i < 4; i++)
#pragma unroll
                    for (int j = 0; j < 4; j++)
                        acc[i][j] = fmaf(a[i], bb[j], acc[i][j]);
            }
            __syncthreads();
        }
    }

#pragma unroll
    for (int i = 0; i < 4; i++) {
        int r = brow + ty * 4 + i;
        if (r >= M) continue;
        int cb = bcol + tx * 4;
        float4 v;
        float* vp = &v.x;
#pragma unroll
        for (int j = 0; j < 4; j++) {
            float x = acc[i][j] + bias[(cb + j) & 2047];
            vp[j] = fmaxf(x, 0.f);
        }
        *reinterpret_cast<float4*>(C + (size_t)r * ldc + cb) = v;
    }
}

// ---------------- Stage 3: cls_part[ks][b][n] = sum_{k-chunk} g[b,k]*k2[n,k] ----------------
__global__ void __launch_bounds__(256)
kernel_D(const float* __restrict__ g, const float* __restrict__ k2) {
    __shared__ __align__(16) float As[16][68];  // [k][b]
    __shared__ __align__(16) float Bs[16][36];  // [k][n]
    const int n0 = blockIdx.x * 32;
    const int ksplit = blockIdx.y;  // 32 splits, chunk = 192
    const int tid = threadIdx.x;
    const int tn = tid & 31;
    const int tg = tid >> 5;
    float acc[8];
#pragma unroll
    for (int j = 0; j < 8; j++) acc[j] = 0.f;
    const int kbase = ksplit * 192;
    for (int kc = 0; kc < 192; kc += 16) {
        const int k0 = kbase + kc;
        {
            int r = tid >> 2, kq = (tid & 3) * 4;
            float4 v = *reinterpret_cast<const float4*>(g + (size_t)r * 6144 + k0 + kq);
            As[kq + 0][r] = v.x; As[kq + 1][r] = v.y; As[kq + 2][r] = v.z; As[kq + 3][r] = v.w;
        }
        if (tid < 128) {
            int n = tid >> 2, kq = (tid & 3) * 4;
            int gn = n0 + n;
            float4 v = make_float4(0.f, 0.f, 0.f, 0.f);
            if (gn < 200) v = *reinterpret_cast<const float4*>(k2 + (size_t)gn * 6144 + k0 + kq);
            Bs[kq + 0][n] = v.x; Bs[kq + 1][n] = v.y; Bs[kq + 2][n] = v.z; Bs[kq + 3][n] = v.w;
        }
        __syncthreads();
#pragma unroll
        for (int k = 0; k < 16; k++) {
            float bv = Bs[k][tn];
            float a[8];
            *reinterpret_cast<float4*>(&a[0]) = *reinterpret_cast<const float4*>(&As[k][tg * 8]);
            *reinterpret_cast<float4*>(&a[4]) = *reinterpret_cast<const float4*>(&As[k][tg * 8 + 4]);
#pragma unroll
            for (int j = 0; j < 8; j++) acc[j] = fmaf(a[j], bv, acc[j]);
        }
        __syncthreads();
    }
    const int gn = n0 + tn;
    if (gn < 200) {
#pragma unroll
        for (int j = 0; j < 8; j++)
            d_part[((size_t)ksplit * 64 + tg * 8 + j) * 200 + gn] = acc[j];
    }
}

__global__ void reduce_D(const float* __restrict__ b_sp) {
    const int i = blockIdx.x * 256 + threadIdx.x;
    if (i < 12800) {
        float s = b_sp[0];
#pragma unroll
        for (int ks = 0; ks < 32; ks++) s += d_part[(size_t)ks * 12800 + i];
        d_cls[i] = s;
    }
}

// ---------------- CosFace epilogue ----------------
__global__ void norms_kernel(const float* __restrict__ wcls) {
    const int w = (blockIdx.x * blockDim.x + threadIdx.x) >> 5;
    const int lane = threadIdx.x & 31;
    if (w >= 264) return;
    const float* row = (w < 64) ? (d_cls + w * 200) : (wcls + (size_t)(w - 64) * 200);
    float s = 0.f;
    for (int t = lane; t < 200; t += 32) { float x = row[t]; s = fmaf(x, x, s); }
    s = wredsum(s);
    if (lane == 0) d_norms[w] = rsqrtf(s);
}

__global__ void cos_kernel(const float* __restrict__ wcls, const int* __restrict__ label,
                           float* __restrict__ out) {
    const int w = (blockIdx.x * blockDim.x + threadIdx.x) >> 5;
    const int lane = threadIdx.x & 31;
    if (w >= 12800) return;
    const int b = w / 200, c = w % 200;
    float s = 0.f;
    for (int t = lane; t < 200; t += 32)
        s = fmaf(d_cls[b * 200 + t], wcls[(size_t)c * 200 + t], s);
    s = wredsum(s);
    if (lane == 0) {
        float cosv = s * d_norms[b] * d_norms[64 + c];
        float m = (label[b] == c) ? 0.5f : 0.f;
        out[b * 200 + c] = 30.f * (cosv - m);
    }
}

// ---------------- launch ----------------
extern "C" void kernel_launch(void* const* d_in, const int* in_sizes, int n_in,
                              void* d_out, int out_size) {
    const float* feat     = (const float*)d_in[0];
    const int*   label    = (const int*)  d_in[1];
    const float* mem_feat = (const float*)d_in[2];
    const float* wt       = (const float*)d_in[3];
    const float* bt       = (const float*)d_in[4];
    const float* wc       = (const float*)d_in[5];
    const float* bc       = (const float*)d_in[6];
    const float* w_sp     = (const float*)d_in[7];
    const float* b_sp     = (const float*)d_in[8];
    const float* w_cls    = (const float*)d_in[9];
    float* out = (float*)d_out;

    float *wtp, *wct, *k1, *k2, *g;
    cudaGetSymbolAddress((void**)&wtp, d_wtp);
    cudaGetSymbolAddress((void**)&wct, d_wct);
    cudaGetSymbolAddress((void**)&k1,  d_k1);
    cudaGetSymbolAddress((void**)&k2,  d_k2);
    cudaGetSymbolAddress((void**)&g,   d_g);

    // layout prep + fused feat reduction (independent of GEMM chain)
    permute_wt_kernel<<<2048, 256>>>(wt, wtp);
    permute_wc_kernel<<<dim3(64, 64), 256>>>(wc);
    g_kernel<<<16384, 256>>>(feat, w_sp);

    // stage 1: k1 = relu(mem_feat @ wtp + bt)   M=200, N=6144, K=2048
    gemm64<<<dim3(96, 4), 256>>>(mem_feat, 2048, wtp, 6144, k1, 6144, 200, 0, bt);

    // stage 2: k2 = relu(conv1d(k1, wc) + bc) as 7 tap-GEMMs (folded per p via blockIdx)
    gemm64<<<dim3(96, 4), 256>>>(k1, 6144, wct, 2048, k2, 6144, 200, 1, bc);

    // stage 3: cls = g . k2^T + b_sp   (split-K 32)
    kernel_D<<<dim3(7, 32), 256>>>(g, k2);
    reduce_D<<<50, 256>>>(b_sp);

    // CosFace
    norms_kernel<<<33, 256>>>(w_cls);
    cos_kernel<<<1600, 256>>>(w_cls, label, out);

    (void)in_sizes; (void)n_in; (void)out_size;
}

// round 4
// speedup vs baseline: 1.8566x; 1.8566x over previous
#include <cuda_runtime.h>
#include <cuda_bf16.h>
#include <cstdint>

#define DI __device__ __forceinline__

// ===================== static scratch (no runtime alloc) =====================
__device__ __nv_bfloat16 d_A1h[256 * 2048];
__device__ __nv_bfloat16 d_A1l[256 * 2048];
__device__ __nv_bfloat16 d_Bt1h[6144u * 2048u];
__device__ __nv_bfloat16 d_Bt1l[6144u * 2048u];
__device__ __nv_bfloat16 d_Bch[3u * 2048u * 2048u];
__device__ __nv_bfloat16 d_Bcl[3u * 2048u * 2048u];
__device__ __nv_bfloat16 d_k1h[256 * 6144];
__device__ __nv_bfloat16 d_k1l[256 * 6144];
__device__ float d_k2[256 * 6144];
__device__ float d_g[64 * 6144];
__device__ float d_part[32 * 64 * 200];
__device__ float d_cls[64 * 200];
__device__ float d_norms[264];

// ===================== PTX helpers =====================
DI uint32_t smem_u32(const void* p) {
    uint32_t a;
    asm("{ .reg .u64 t; cvta.to.shared.u64 t, %1; cvt.u32.u64 %0, t; }" : "=r"(a) : "l"(p));
    return a;
}
DI void cp16(uint32_t dst, const void* src) {
    asm volatile("cp.async.cg.shared.global [%0], [%1], 16;" :: "r"(dst), "l"(src) : "memory");
}
DI void cp_commit() { asm volatile("cp.async.commit_group;" ::: "memory"); }
DI void cp_wait1()  { asm volatile("cp.async.wait_group 1;" ::: "memory"); }
DI void cp_wait0()  { asm volatile("cp.async.wait_group 0;" ::: "memory"); }

DI void ldsm4(uint32_t* r, uint32_t addr) {
    asm volatile("ldmatrix.sync.aligned.m8n8.x4.shared.b16 {%0,%1,%2,%3}, [%4];"
        : "=r"(r[0]), "=r"(r[1]), "=r"(r[2]), "=r"(r[3]) : "r"(addr));
}

// m16n8k16 bf16 mma, fp32 accum (baseline sm_80+ PTX, runs on tensor pipe)
DI void mma_bf16(float* c, const uint32_t* a, const uint32_t* b) {
    asm volatile(
        "mma.sync.aligned.m16n8k16.row.col.f32.bf16.bf16.f32 "
        "{%0,%1,%2,%3}, {%4,%5,%6,%7}, {%8,%9}, {%0,%1,%2,%3};"
        : "+f"(c[0]), "+f"(c[1]), "+f"(c[2]), "+f"(c[3])
        : "r"(a[0]), "r"(a[1]), "r"(a[2]), "r"(a[3]), "r"(b[0]), "r"(b[1]));
}

DI float wredsum(float v) {
#pragma unroll
    for (int o = 16; o > 0; o >>= 1) v += __shfl_xor_sync(0xffffffffu, v, o);
    return v;
}

// ===================== prep kernels =====================
__global__ void prep_A1(const float* __restrict__ mem_feat) {
    int idx = blockIdx.x * 256 + threadIdx.x;
    if (idx >= 256 * 2048) return;
    int row = idx >> 11;
    float x = (row < 200) ? mem_feat[(size_t)row * 2048 + (idx & 2047)] : 0.f;
    __nv_bfloat16 h = __float2bfloat16(x);
    d_A1h[idx] = h;
    d_A1l[idx] = __float2bfloat16(x - __bfloat162float(h));
}

// Bt1[m][i] = wt[i][(m&2047)*3 + (m>>11)]
__global__ void prep_Bt1(const float* __restrict__ wt) {
    __shared__ float s[32][97];
    const int m0 = blockIdx.x * 32;
    const int i0 = blockIdx.y * 32;
    const int p = m0 >> 11;
    const int o0 = m0 & 2047;
    const float* src = wt + (size_t)i0 * 6144 + (size_t)o0 * 3;
    for (int v = threadIdx.x; v < 768; v += 256) {
        int ii = v / 24, c4 = v % 24;
        float4 val = *reinterpret_cast<const float4*>(src + (size_t)ii * 6144 + c4 * 4);
        s[ii][c4 * 4 + 0] = val.x; s[ii][c4 * 4 + 1] = val.y;
        s[ii][c4 * 4 + 2] = val.z; s[ii][c4 * 4 + 3] = val.w;
    }
    __syncthreads();
    for (int v = threadIdx.x; v < 1024; v += 256) {
        int ml = v >> 5, il = v & 31;
        float x = s[il][ml * 3 + p];
        __nv_bfloat16 h = __float2bfloat16(x);
        size_t idx = (size_t)(m0 + ml) * 2048 + i0 + il;
        d_Bt1h[idx] = h;
        d_Bt1l[idx] = __float2bfloat16(x - __bfloat162float(h));
    }
}

// Bc[q][o][i] = wc[o][i*3+q]
__global__ void prep_Bc(const float* __restrict__ wc) {
    int idx = blockIdx.x * 256 + threadIdx.x;
    if (idx >= 2048 * 2048) return;
    int o = idx >> 11, i = idx & 2047;
    const float* r = wc + (size_t)o * 6144 + (size_t)i * 3;
#pragma unroll
    for (int q = 0; q < 3; q++) {
        float x = r[q];
        __nv_bfloat16 h = __float2bfloat16(x);
        size_t didx = (size_t)q * 4194304u + (size_t)idx;
        d_Bch[didx] = h;
        d_Bcl[didx] = __float2bfloat16(x - __bfloat162float(h));
    }
}

// g[b][q*2048+c] = sum_s w_sp[s]*feat[b,c,s+q-1]
__global__ void g_kernel(const float* __restrict__ feat, const float* __restrict__ w_sp) {
    __shared__ float ws[200];
    const int tid = threadIdx.x;
    if (tid < 198) {
        float v = 0.f;
        if (tid >= 1 && tid <= 196) v = w_sp[tid - 1];
        ws[tid] = v;
    }
    __syncthreads();
    const int w = blockIdx.x * 8 + (tid >> 5);
    const int lane = tid & 31;
    const int b = w >> 11;
    const int c = w & 2047;
    const float* x = feat + ((size_t)b * 2048 + c) * 196;
    float a0 = 0.f, a1 = 0.f, a2 = 0.f;
    for (int t = lane; t < 196; t += 32) {
        float xv = x[t];
        a0 = fmaf(xv, ws[t + 2], a0);
        a1 = fmaf(xv, ws[t + 1], a1);
        a2 = fmaf(xv, ws[t], a2);
    }
    a0 = wredsum(a0); a1 = wredsum(a1); a2 = wredsum(a2);
    if (lane == 0) {
        d_g[(size_t)b * 6144 + c] = a0;
        d_g[(size_t)b * 6144 + 2048 + c] = a1;
        d_g[(size_t)b * 6144 + 4096 + c] = a2;
    }
}

// ===================== HMMA GEMM: 128x128 tile, BK=64, bf16 hi/lo split =====================
// smem per buffer: Ah,Al,Bh,Bl each 128 rows x 128B (16KB) -> 64KB; double buffered -> 128KB
static constexpr int SMEM_BYTES = 2 * 65536 + 1024;

// swizzled offset within a 16KB operand region: row r (0..127), 16B-group g (0..7)
DI uint32_t swz(int r, int g) {
    return ((uint32_t)r << 7) + (((uint32_t)(g ^ (r & 7))) << 4);
}

// stage 0: k1 = relu(A1 @ Bt1^T + bt)  -> d_k1h/d_k1l (bf16 hi/lo)
// stage 1: k2 = relu(conv taps(k1, Bc) + bc) -> d_k2 (fp32)
__global__ void __launch_bounds__(256, 1)
gemm_mma(const __nv_bfloat16* __restrict__ Ah, const __nv_bfloat16* __restrict__ Al, int lda,
         const __nv_bfloat16* __restrict__ Bh, const __nv_bfloat16* __restrict__ Bl,
         const float* __restrict__ bias, int stage)
{
    extern __shared__ char dsm[];
    __shared__ float sBias[128];

    const int tid = threadIdx.x;
    const int m0 = blockIdx.y * 128;
    const int bcol = blockIdx.x * 128;
    const int o0 = bcol & 2047;

    const uint32_t dsm_u = smem_u32(dsm);
    const uint32_t dbase = (dsm_u + 1023u) & ~1023u;

    if (tid < 128) sBias[tid] = bias[o0 + tid];

    // conv-tap segments: j = input position block, q = kernel tap
    int nseg;
    int aoff[3];
    size_t boff[3];
    int brow0;
    if (stage) {
        const int p = bcol >> 11;
        int js[3], qs[3];
        if (p == 0)      { nseg = 2; js[0] = 0; js[1] = 1; js[2] = 0; qs[0] = 1; qs[1] = 2; qs[2] = 0; }
        else if (p == 1) { nseg = 3; js[0] = 0; js[1] = 1; js[2] = 2; qs[0] = 0; qs[1] = 1; qs[2] = 2; }
        else             { nseg = 2; js[0] = 1; js[1] = 2; js[2] = 0; qs[0] = 0; qs[1] = 1; qs[2] = 0; }
#pragma unroll
        for (int s = 0; s < 3; s++) { aoff[s] = js[s] * 2048; boff[s] = (size_t)qs[s] * 4194304u; }
        brow0 = o0;
    } else {
        nseg = 1;
        aoff[0] = 0; boff[0] = 0;
        aoff[1] = aoff[2] = 0; boff[1] = boff[2] = 0;
        brow0 = bcol;
    }
    const int nch = nseg * 32;   // 64-wide K chunks

    // ---- loader geometry: 256 threads, 2 per row; each thread 4 x 16B groups per operand
    const int lrow = tid >> 1;               // 0..127
    const int gset = (tid & 1) * 4;          // groups gset..gset+3
    const size_t aRowB = (size_t)(m0 + lrow) * lda;
    const size_t bRowB = (size_t)(brow0 + lrow) * 2048;

    // ---- compute geometry: 8 warps as 4(m) x 2(n)
    const int lane = tid & 31;
    const int warp = tid >> 5;
    const int m0w = (warp & 3) * 32;
    const int n0w = (warp >> 2) * 64;
    const int lr = lane & 15;
    const int kb = lane >> 4;   // extra k-group for ldmatrix octets 2,3

    float acc[2][8][4];
#pragma unroll
    for (int t = 0; t < 2; t++)
#pragma unroll
        for (int n = 0; n < 8; n++)
#pragma unroll
            for (int j = 0; j < 4; j++) acc[t][n][j] = 0.f;

    // ---- chunk loader (cp.async): operand regions Ah|Al|Bh|Bl at +0,+16K,+32K,+48K
#define LOADC(cc, bb) do { \
    const int _s = (cc) >> 5; \
    const int _kc = ((cc) & 31) << 6; \
    const uint32_t _b0 = dbase + (uint32_t)(bb) * 65536u; \
    const __nv_bfloat16* _ah = Ah + aRowB + aoff[_s] + _kc; \
    const __nv_bfloat16* _al = Al + aRowB + aoff[_s] + _kc; \
    const __nv_bfloat16* _bh = Bh + boff[_s] + bRowB + _kc; \
    const __nv_bfloat16* _bl = Bl + boff[_s] + bRowB + _kc; \
    _Pragma("unroll") \
    for (int _j = 0; _j < 4; _j++) { \
        const int _g = gset + _j; \
        const uint32_t _o = swz(lrow, _g); \
        cp16(_b0 + _o,           _ah + _g * 8); \
        cp16(_b0 + 16384u + _o,  _al + _g * 8); \
        cp16(_b0 + 32768u + _o,  _bh + _g * 8); \
        cp16(_b0 + 49152u + _o,  _bl + _g * 8); \
    } \
    cp_commit(); \
} while (0)

    LOADC(0, 0);

    for (int c = 0; c < nch; ++c) {
        if (c + 1 < nch) { LOADC(c + 1, (c + 1) & 1); cp_wait1(); }
        else             { cp_wait0(); }
        __syncthreads();

        const uint32_t bb = dbase + (uint32_t)(c & 1) * 65536u;
        const uint32_t sAh = bb, sAl = bb + 16384u, sBh = bb + 32768u, sBl = bb + 49152u;

#pragma unroll
        for (int kk = 0; kk < 4; kk++) {
            const int gk = (kk << 1) | kb;
            uint32_t ah[2][4], al[2][4];
#pragma unroll
            for (int t = 0; t < 2; t++) {
                const int r = m0w + t * 16 + lr;
                const uint32_t off = swz(r, gk);
                ldsm4(ah[t], sAh + off);
                ldsm4(al[t], sAl + off);
            }
#pragma unroll
            for (int nt2 = 0; nt2 < 4; nt2++) {
                const int r = n0w + nt2 * 16 + lr;
                const uint32_t off = swz(r, gk);
                uint32_t bh[4], bl[4];
                ldsm4(bh, sBh + off);
                ldsm4(bl, sBl + off);
                uint32_t bh0[2] = {bh[0], bh[2]};
                uint32_t bh1[2] = {bh[1], bh[3]};
                uint32_t bl0[2] = {bl[0], bl[2]};
                uint32_t bl1[2] = {bl[1], bl[3]};
#pragma unroll
                for (int t = 0; t < 2; t++) {
                    mma_bf16(acc[t][2 * nt2],     ah[t], bh0);
                    mma_bf16(acc[t][2 * nt2],     al[t], bh0);
                    mma_bf16(acc[t][2 * nt2],     ah[t], bl0);
                    mma_bf16(acc[t][2 * nt2 + 1], ah[t], bh1);
                    mma_bf16(acc[t][2 * nt2 + 1], al[t], bh1);
                    mma_bf16(acc[t][2 * nt2 + 1], ah[t], bl1);
                }
            }
        }
        __syncthreads();
    }
#undef LOADC

    // ---- epilogue: bias + relu, direct stores ----
    const int mrow = lane >> 2;
    const int npair = 2 * (lane & 3);
#pragma unroll
    for (int t = 0; t < 2; t++) {
#pragma unroll
        for (int nt = 0; nt < 8; nt++) {
            const int nloc = n0w + nt * 8 + npair;
            const float b0 = sBias[nloc], b1 = sBias[nloc + 1];
            const int mA = m0 + m0w + t * 16 + mrow;
            const float v0 = fmaxf(acc[t][nt][0] + b0, 0.f);
            const float v1 = fmaxf(acc[t][nt][1] + b1, 0.f);
            const float v2 = fmaxf(acc[t][nt][2] + b0, 0.f);
            const float v3 = fmaxf(acc[t][nt][3] + b1, 0.f);
            const size_t i0 = (size_t)mA * 6144 + bcol + nloc;
            const size_t i1 = (size_t)(mA + 8) * 6144 + bcol + nloc;
            if (stage == 0) {
                __nv_bfloat162 h0 = __floats2bfloat162_rn(v0, v1);
                __nv_bfloat162 h1 = __floats2bfloat162_rn(v2, v3);
                __nv_bfloat162 l0 = __floats2bfloat162_rn(v0 - __bfloat162float(h0.x),
                                                          v1 - __bfloat162float(h0.y));
                __nv_bfloat162 l1 = __floats2bfloat162_rn(v2 - __bfloat162float(h1.x),
                                                          v3 - __bfloat162float(h1.y));
                *reinterpret_cast<__nv_bfloat162*>(d_k1h + i0) = h0;
                *reinterpret_cast<__nv_bfloat162*>(d_k1h + i1) = h1;
                *reinterpret_cast<__nv_bfloat162*>(d_k1l + i0) = l0;
                *reinterpret_cast<__nv_bfloat162*>(d_k1l + i1) = l1;
            } else {
                *reinterpret_cast<float2*>(d_k2 + i0) = make_float2(v0, v1);
                *reinterpret_cast<float2*>(d_k2 + i1) = make_float2(v2, v3);
            }
        }
    }
}

// ===================== stage 3: cls = g . k2^T + b_sp (split-K) =====================
__global__ void __launch_bounds__(256)
kernel_D(const float* __restrict__ g, const float* __restrict__ k2) {
    __shared__ __align__(16) float As[16][68];
    __shared__ __align__(16) float Bs[16][36];
    const int n0 = blockIdx.x * 32;
    const int ksplit = blockIdx.y;
    const int tid = threadIdx.x;
    const int tn = tid & 31;
    const int tg = tid >> 5;
    float acc[8];
#pragma unroll
    for (int j = 0; j < 8; j++) acc[j] = 0.f;
    const int kbase = ksplit * 192;
    for (int kc = 0; kc < 192; kc += 16) {
        const int k0 = kbase + kc;
        {
            int r = tid >> 2, kq = (tid & 3) * 4;
            float4 v = *reinterpret_cast<const float4*>(g + (size_t)r * 6144 + k0 + kq);
            As[kq + 0][r] = v.x; As[kq + 1][r] = v.y; As[kq + 2][r] = v.z; As[kq + 3][r] = v.w;
        }
        if (tid < 128) {
            int n = tid >> 2, kq = (tid & 3) * 4;
            int gn = n0 + n;
            float4 v = make_float4(0.f, 0.f, 0.f, 0.f);
            if (gn < 200) v = *reinterpret_cast<const float4*>(k2 + (size_t)gn * 6144 + k0 + kq);
            Bs[kq + 0][n] = v.x; Bs[kq + 1][n] = v.y; Bs[kq + 2][n] = v.z; Bs[kq + 3][n] = v.w;
        }
        __syncthreads();
#pragma unroll
        for (int k = 0; k < 16; k++) {
            float bv = Bs[k][tn];
            float a[8];
            *reinterpret_cast<float4*>(&a[0]) = *reinterpret_cast<const float4*>(&As[k][tg * 8]);
            *reinterpret_cast<float4*>(&a[4]) = *reinterpret_cast<const float4*>(&As[k][tg * 8 + 4]);
#pragma unroll
            for (int j = 0; j < 8; j++) acc[j] = fmaf(a[j], bv, acc[j]);
        }
        __syncthreads();
    }
    const int gn = n0 + tn;
    if (gn < 200) {
#pragma unroll
        for (int j = 0; j < 8; j++)
            d_part[((size_t)ksplit * 64 + tg * 8 + j) * 200 + gn] = acc[j];
    }
}

__global__ void reduce_D(const float* __restrict__ b_sp) {
    const int i = blockIdx.x * 256 + threadIdx.x;
    if (i < 12800) {
        float s = b_sp[0];
#pragma unroll
        for (int ks = 0; ks < 32; ks++) s += d_part[(size_t)ks * 12800 + i];
        d_cls[i] = s;
    }
}

// ===================== CosFace epilogue =====================
__global__ void norms_kernel(const float* __restrict__ wcls) {
    const int w = (blockIdx.x * blockDim.x + threadIdx.x) >> 5;
    const int lane = threadIdx.x & 31;
    if (w >= 264) return;
    const float* row = (w < 64) ? (d_cls + w * 200) : (wcls + (size_t)(w - 64) * 200);
    float s = 0.f;
    for (int t = lane; t < 200; t += 32) { float x = row[t]; s = fmaf(x, x, s); }
    s = wredsum(s);
    if (lane == 0) d_norms[w] = rsqrtf(s);
}

__global__ void cos_kernel(const float* __restrict__ wcls, const int* __restrict__ label,
                           float* __restrict__ out) {
    const int w = (blockIdx.x * blockDim.x + threadIdx.x) >> 5;
    const int lane = threadIdx.x & 31;
    if (w >= 12800) return;
    const int b = w / 200, c = w % 200;
    float s = 0.f;
    for (int t = lane; t < 200; t += 32)
        s = fmaf(d_cls[b * 200 + t], wcls[(size_t)c * 200 + t], s);
    s = wredsum(s);
    if (lane == 0) {
        float cosv = s * d_norms[b] * d_norms[64 + c];
        float m = (label[b] == c) ? 0.5f : 0.f;
        out[b * 200 + c] = 30.f * (cosv - m);
    }
}

// ===================== launch =====================
extern "C" void kernel_launch(void* const* d_in, const int* in_sizes, int n_in,
                              void* d_out, int out_size) {
    const float* feat     = (const float*)d_in[0];
    const int*   label    = (const int*)  d_in[1];
    const float* mem_feat = (const float*)d_in[2];
    const float* wt       = (const float*)d_in[3];
    const float* bt       = (const float*)d_in[4];
    const float* wc       = (const float*)d_in[5];
    const float* bc       = (const float*)d_in[6];
    const float* w_sp     = (const float*)d_in[7];
    const float* b_sp     = (const float*)d_in[8];
    const float* w_cls    = (const float*)d_in[9];
    float* out = (float*)d_out;

    cudaFuncSetAttribute(gemm_mma, cudaFuncAttributeMaxDynamicSharedMemorySize, SMEM_BYTES);

    __nv_bfloat16 *A1h, *A1l, *Bt1h, *Bt1l, *Bch, *Bcl, *k1h, *k1l;
    float *k2, *g;
    cudaGetSymbolAddress((void**)&A1h,  d_A1h);
    cudaGetSymbolAddress((void**)&A1l,  d_A1l);
    cudaGetSymbolAddress((void**)&Bt1h, d_Bt1h);
    cudaGetSymbolAddress((void**)&Bt1l, d_Bt1l);
    cudaGetSymbolAddress((void**)&Bch,  d_Bch);
    cudaGetSymbolAddress((void**)&Bcl,  d_Bcl);
    cudaGetSymbolAddress((void**)&k1h,  d_k1h);
    cudaGetSymbolAddress((void**)&k1l,  d_k1l);
    cudaGetSymbolAddress((void**)&k2,   d_k2);
    cudaGetSymbolAddress((void**)&g,    d_g);

    // operand prep (independent) + fused feat reduction
    prep_A1<<<2048, 256>>>(mem_feat);
    prep_Bt1<<<dim3(192, 64), 256>>>(wt);
    prep_Bc<<<16384, 256>>>(wc);
    g_kernel<<<16384, 256>>>(feat, w_sp);

    // stage 1: k1 = relu(A1 @ Bt1^T + bt), M=256, N=6144, K=2048
    gemm_mma<<<dim3(48, 2), 256, SMEM_BYTES>>>(A1h, A1l, 2048, Bt1h, Bt1l, bt, 0);
    // stage 2: k2 = relu(conv taps + bc), 2-3 K-segments per p block
    gemm_mma<<<dim3(48, 2), 256, SMEM_BYTES>>>(k1h, k1l, 6144, Bch, Bcl, bc, 1);

    // stage 3 + CosFace
    kernel_D<<<dim3(7, 32), 256>>>(g, k2);
    reduce_D<<<50, 256>>>(b_sp);
    norms_kernel<<<33, 256>>>(w_cls);
    cos_kernel<<<1600, 256>>>(w_cls, label, out);

    (void)in_sizes; (void)n_in; (void)out_size;
}

// round 5
// speedup vs baseline: 2.3982x; 1.2917x over previous
#include <cuda_runtime.h>
#include <cuda_bf16.h>
#include <cstdint>

#define DI __device__ __forceinline__

// ===================== static scratch (no runtime alloc) =====================
__device__ __nv_bfloat16 d_A1h[256 * 2048];
__device__ __nv_bfloat16 d_A1l[256 * 2048];
__device__ __nv_bfloat16 d_Bt1h[6144u * 2048u];
__device__ __nv_bfloat16 d_Bt1l[6144u * 2048u];
__device__ __nv_bfloat16 d_Bch[3u * 2048u * 2048u];
__device__ __nv_bfloat16 d_Bcl[3u * 2048u * 2048u];
__device__ __nv_bfloat16 d_k1h[256 * 6144];
__device__ __nv_bfloat16 d_k1l[256 * 6144];
__device__ float d_p2[3u * 256u * 6144u];   // stage2 tap partials
__device__ float d_k2[256 * 6144];
__device__ float d_g[64 * 6144];
__device__ float d_part[32 * 64 * 200];
__device__ float d_cls[64 * 200];
__device__ float d_norms[264];

// ===================== PTX helpers =====================
DI uint32_t smem_u32(const void* p) {
    uint32_t a;
    asm("{ .reg .u64 t; cvta.to.shared.u64 t, %1; cvt.u32.u64 %0, t; }" : "=r"(a) : "l"(p));
    return a;
}
DI void cp16(uint32_t dst, const void* src) {
    asm volatile("cp.async.cg.shared.global [%0], [%1], 16;" :: "r"(dst), "l"(src) : "memory");
}
DI void cp_commit() { asm volatile("cp.async.commit_group;" ::: "memory"); }
DI void cp_wait1()  { asm volatile("cp.async.wait_group 1;" ::: "memory"); }
DI void cp_wait0()  { asm volatile("cp.async.wait_group 0;" ::: "memory"); }

DI void ldsm4(uint32_t* r, uint32_t addr) {
    asm volatile("ldmatrix.sync.aligned.m8n8.x4.shared.b16 {%0,%1,%2,%3}, [%4];"
        : "=r"(r[0]), "=r"(r[1]), "=r"(r[2]), "=r"(r[3]) : "r"(addr));
}

// m16n8k16 bf16 mma, fp32 accum
DI void mma_bf16(float* c, const uint32_t* a, const uint32_t* b) {
    asm volatile(
        "mma.sync.aligned.m16n8k16.row.col.f32.bf16.bf16.f32 "
        "{%0,%1,%2,%3}, {%4,%5,%6,%7}, {%8,%9}, {%0,%1,%2,%3};"
        : "+f"(c[0]), "+f"(c[1]), "+f"(c[2]), "+f"(c[3])
        : "r"(a[0]), "r"(a[1]), "r"(a[2]), "r"(a[3]), "r"(b[0]), "r"(b[1]));
}

DI float wredsum(float v) {
#pragma unroll
    for (int o = 16; o > 0; o >>= 1) v += __shfl_xor_sync(0xffffffffu, v, o);
    return v;
}

// ===================== prep kernels =====================
__global__ void prep_A1(const float* __restrict__ mem_feat) {
    int idx = blockIdx.x * 256 + threadIdx.x;
    if (idx >= 256 * 2048) return;
    int row = idx >> 11;
    float x = (row < 200) ? mem_feat[(size_t)row * 2048 + (idx & 2047)] : 0.f;
    __nv_bfloat16 h = __float2bfloat16(x);
    d_A1h[idx] = h;
    d_A1l[idx] = __float2bfloat16(x - __bfloat162float(h));
}

// Bt1[m][i] = wt[i][(m&2047)*3 + (m>>11)]
__global__ void prep_Bt1(const float* __restrict__ wt) {
    __shared__ float s[32][97];
    const int m0 = blockIdx.x * 32;
    const int i0 = blockIdx.y * 32;
    const int p = m0 >> 11;
    const int o0 = m0 & 2047;
    const float* src = wt + (size_t)i0 * 6144 + (size_t)o0 * 3;
    for (int v = threadIdx.x; v < 768; v += 256) {
        int ii = v / 24, c4 = v % 24;
        float4 val = *reinterpret_cast<const float4*>(src + (size_t)ii * 6144 + c4 * 4);
        s[ii][c4 * 4 + 0] = val.x; s[ii][c4 * 4 + 1] = val.y;
        s[ii][c4 * 4 + 2] = val.z; s[ii][c4 * 4 + 3] = val.w;
    }
    __syncthreads();
    for (int v = threadIdx.x; v < 1024; v += 256) {
        int ml = v >> 5, il = v & 31;
        float x = s[il][ml * 3 + p];
        __nv_bfloat16 h = __float2bfloat16(x);
        size_t idx = (size_t)(m0 + ml) * 2048 + i0 + il;
        d_Bt1h[idx] = h;
        d_Bt1l[idx] = __float2bfloat16(x - __bfloat162float(h));
    }
}

// Bc[q][o][i] = wc[o][i*3+q]
__global__ void prep_Bc(const float* __restrict__ wc) {
    int idx = blockIdx.x * 256 + threadIdx.x;
    if (idx >= 2048 * 2048) return;
    int o = idx >> 11, i = idx & 2047;
    const float* r = wc + (size_t)o * 6144 + (size_t)i * 3;
#pragma unroll
    for (int q = 0; q < 3; q++) {
        float x = r[q];
        __nv_bfloat16 h = __float2bfloat16(x);
        size_t didx = (size_t)q * 4194304u + (size_t)idx;
        d_Bch[didx] = h;
        d_Bcl[didx] = __float2bfloat16(x - __bfloat162float(h));
    }
}

// g[b][q*2048+c] = sum_s w_sp[s]*feat[b,c,s+q-1]  (unrolled: 7 batched LDGs)
__global__ void g_kernel(const float* __restrict__ feat, const float* __restrict__ w_sp) {
    __shared__ float ws[200];
    const int tid = threadIdx.x;
    if (tid < 198) {
        float v = 0.f;
        if (tid >= 1 && tid <= 196) v = w_sp[tid - 1];
        ws[tid] = v;
    }
    __syncthreads();
    const int w = blockIdx.x * 8 + (tid >> 5);
    const int lane = tid & 31;
    const int b = w >> 11;
    const int c = w & 2047;
    const float* x = feat + ((size_t)b * 2048 + c) * 196;

    float xv[6];
#pragma unroll
    for (int k = 0; k < 6; k++) xv[k] = x[lane + 32 * k];
    float x6 = (lane < 4) ? x[192 + lane] : 0.f;

    float a0 = 0.f, a1 = 0.f, a2 = 0.f;
#pragma unroll
    for (int k = 0; k < 6; k++) {
        const int t = lane + 32 * k;
        a0 = fmaf(xv[k], ws[t + 2], a0);
        a1 = fmaf(xv[k], ws[t + 1], a1);
        a2 = fmaf(xv[k], ws[t],     a2);
    }
    if (lane < 4) {
        const int t = 192 + lane;
        a0 = fmaf(x6, ws[t + 2], a0);
        a1 = fmaf(x6, ws[t + 1], a1);
        a2 = fmaf(x6, ws[t],     a2);
    }
    a0 = wredsum(a0); a1 = wredsum(a1); a2 = wredsum(a2);
    if (lane == 0) {
        d_g[(size_t)b * 6144 + c]        = a0;
        d_g[(size_t)b * 6144 + 2048 + c] = a1;
        d_g[(size_t)b * 6144 + 4096 + c] = a2;
    }
}

// ===================== HMMA tap-GEMM: 128x128 tile, one K=2048 segment, 3-stage pipe =====================
static constexpr int SMEM_BYTES = 3 * 65536 + 1024;

DI uint32_t swz(int r, int g) {
    return ((uint32_t)r << 7) + (((uint32_t)(g ^ (r & 7))) << 4);
}

// mode 0 (stage1 tile): C = relu(A@B^T + bias) -> d_k1h/d_k1l (bf16 hi/lo)
// mode 1 (stage2 tap):  C = A@B^T raw fp32 -> d_p2[slot]
__global__ void __launch_bounds__(256, 1)
gemm_tap(const __nv_bfloat16* __restrict__ Ah, const __nv_bfloat16* __restrict__ Al, int lda,
         const __nv_bfloat16* __restrict__ Bh, const __nv_bfloat16* __restrict__ Bl,
         const float* __restrict__ bias, int mode)
{
    extern __shared__ char dsm[];
    __shared__ float sBias[128];

    const int tid = threadIdx.x;
    const int bx = blockIdx.x;
    const int m0 = blockIdx.y * 128;

    // unit geometry
    size_t aBase, bBase;
    int outcol, slot;
    if (mode == 0) {
        aBase = 0;
        bBase = (size_t)bx * 128u * 2048u;
        outcol = bx * 128;
        slot = 0;
    } else {
        const int tap = bx >> 4;
        const int ct = bx & 15;
        int p, s, j, q;
        if (tap < 2)      { p = 0; s = tap;     j = tap;   q = tap + 1; }
        else if (tap < 5) { p = 1; s = tap - 2; j = s;     q = s; }
        else              { p = 2; s = tap - 5; j = s + 1; q = s; }
        aBase = (size_t)j * 2048u;
        bBase = (size_t)q * 4194304u + (size_t)(ct * 128) * 2048u;
        outcol = p * 2048 + ct * 128;
        slot = s;
    }

    const uint32_t dsm_u = smem_u32(dsm);
    const uint32_t dbase = (dsm_u + 1023u) & ~1023u;

    if (mode == 0 && tid < 128) sBias[tid] = bias[(outcol & 2047) + tid];

    // loader geometry: 2 threads/row, 4 x 16B groups each, 4 operand regions
    const int lrow = tid >> 1;
    const int gset = (tid & 1) * 4;
    const size_t aRowB = (size_t)(m0 + lrow) * lda + aBase;
    const size_t bRowB = bBase + (size_t)lrow * 2048u;

    // compute geometry: 8 warps as 4(m) x 2(n)
    const int lane = tid & 31;
    const int warp = tid >> 5;
    const int m0w = (warp & 3) * 32;
    const int n0w = (warp >> 2) * 64;
    const int lr = lane & 15;
    const int kb = lane >> 4;

    float acc[2][8][4];
#pragma unroll
    for (int t = 0; t < 2; t++)
#pragma unroll
        for (int n = 0; n < 8; n++)
#pragma unroll
            for (int j = 0; j < 4; j++) acc[t][n][j] = 0.f;

#define LOADC(cc, bb) do { \
    const int _kc = (cc) << 6; \
    const uint32_t _b0 = dbase + (uint32_t)(bb) * 65536u; \
    const __nv_bfloat16* _ah = Ah + aRowB + _kc; \
    const __nv_bfloat16* _al = Al + aRowB + _kc; \
    const __nv_bfloat16* _bh = Bh + bRowB + _kc; \
    const __nv_bfloat16* _bl = Bl + bRowB + _kc; \
    _Pragma("unroll") \
    for (int _j = 0; _j < 4; _j++) { \
        const int _g = gset + _j; \
        const uint32_t _o = swz(lrow, _g); \
        cp16(_b0 + _o,           _ah + _g * 8); \
        cp16(_b0 + 16384u + _o,  _al + _g * 8); \
        cp16(_b0 + 32768u + _o,  _bh + _g * 8); \
        cp16(_b0 + 49152u + _o,  _bl + _g * 8); \
    } \
    cp_commit(); \
} while (0)

    LOADC(0, 0);
    LOADC(1, 1);

    for (int c = 0; c < 32; ++c) {
        if (c < 31) cp_wait1(); else cp_wait0();
        __syncthreads();
        if (c + 2 < 32) LOADC(c + 2, (c + 2) % 3);

        const uint32_t bb = dbase + (uint32_t)(c % 3) * 65536u;
        const uint32_t sAh = bb, sAl = bb + 16384u, sBh = bb + 32768u, sBl = bb + 49152u;

#pragma unroll
        for (int kk = 0; kk < 4; kk++) {
            const int gk = (kk << 1) | kb;
            uint32_t ah[2][4], al[2][4];
#pragma unroll
            for (int t = 0; t < 2; t++) {
                const int r = m0w + t * 16 + lr;
                const uint32_t off = swz(r, gk);
                ldsm4(ah[t], sAh + off);
                ldsm4(al[t], sAl + off);
            }
#pragma unroll
            for (int nt2 = 0; nt2 < 4; nt2++) {
                const int r = n0w + nt2 * 16 + lr;
                const uint32_t off = swz(r, gk);
                uint32_t bh[4], bl[4];
                ldsm4(bh, sBh + off);
                ldsm4(bl, sBl + off);
                uint32_t bh0[2] = {bh[0], bh[2]};
                uint32_t bh1[2] = {bh[1], bh[3]};
                uint32_t bl0[2] = {bl[0], bl[2]};
                uint32_t bl1[2] = {bl[1], bl[3]};
#pragma unroll
                for (int t = 0; t < 2; t++) {
                    mma_bf16(acc[t][2 * nt2],     ah[t], bh0);
                    mma_bf16(acc[t][2 * nt2],     al[t], bh0);
                    mma_bf16(acc[t][2 * nt2],     ah[t], bl0);
                    mma_bf16(acc[t][2 * nt2 + 1], ah[t], bh1);
                    mma_bf16(acc[t][2 * nt2 + 1], al[t], bh1);
                    mma_bf16(acc[t][2 * nt2 + 1], ah[t], bl1);
                }
            }
        }
    }
#undef LOADC

    // ---- epilogue ----
    const int mrow = lane >> 2;
    const int npair = 2 * (lane & 3);
#pragma unroll
    for (int t = 0; t < 2; t++) {
#pragma unroll
        for (int nt = 0; nt < 8; nt++) {
            const int nloc = n0w + nt * 8 + npair;
            const int mA = m0 + m0w + t * 16 + mrow;
            if (mode == 0) {
                const float b0 = sBias[nloc], b1 = sBias[nloc + 1];
                const float v0 = fmaxf(acc[t][nt][0] + b0, 0.f);
                const float v1 = fmaxf(acc[t][nt][1] + b1, 0.f);
                const float v2 = fmaxf(acc[t][nt][2] + b0, 0.f);
                const float v3 = fmaxf(acc[t][nt][3] + b1, 0.f);
                const size_t i0 = (size_t)mA * 6144 + outcol + nloc;
                const size_t i1 = (size_t)(mA + 8) * 6144 + outcol + nloc;
                __nv_bfloat162 h0 = __floats2bfloat162_rn(v0, v1);
                __nv_bfloat162 h1 = __floats2bfloat162_rn(v2, v3);
                __nv_bfloat162 l0 = __floats2bfloat162_rn(v0 - __bfloat162float(h0.x),
                                                          v1 - __bfloat162float(h0.y));
                __nv_bfloat162 l1 = __floats2bfloat162_rn(v2 - __bfloat162float(h1.x),
                                                          v3 - __bfloat162float(h1.y));
                *reinterpret_cast<__nv_bfloat162*>(d_k1h + i0) = h0;
                *reinterpret_cast<__nv_bfloat162*>(d_k1h + i1) = h1;
                *reinterpret_cast<__nv_bfloat162*>(d_k1l + i0) = l0;
                *reinterpret_cast<__nv_bfloat162*>(d_k1l + i1) = l1;
            } else {
                const size_t base = (size_t)slot * 1572864u + (size_t)mA * 6144 + outcol + nloc;
                *reinterpret_cast<float2*>(d_p2 + base) =
                    make_float2(acc[t][nt][0], acc[t][nt][1]);
                *reinterpret_cast<float2*>(d_p2 + base + 8u * 6144u) =
                    make_float2(acc[t][nt][2], acc[t][nt][3]);
            }
        }
    }
}

// ===================== stage2 epilogue: k2 = relu(sum partials + bc) =====================
__global__ void epi2(const float* __restrict__ bc) {
    const int idx = blockIdx.x * 256 + threadIdx.x;   // over 200*1536 float4s
    if (idx >= 200 * 1536) return;
    const int m = idx / 1536;
    const int c4 = idx - m * 1536;
    const int col = c4 * 4;
    const int p = col >> 11;
    const int o = col & 2047;
    const float4* P = reinterpret_cast<const float4*>(d_p2);
    const size_t off = (size_t)m * 1536 + c4;
    float4 v0 = P[off];
    float4 v1 = P[393216u + off];
    float rx = v0.x + v1.x, ry = v0.y + v1.y, rz = v0.z + v1.z, rw = v0.w + v1.w;
    if (p == 1) {
        float4 v2 = P[786432u + off];
        rx += v2.x; ry += v2.y; rz += v2.z; rw += v2.w;
    }
    float4 r;
    r.x = fmaxf(rx + bc[o],     0.f);
    r.y = fmaxf(ry + bc[o + 1], 0.f);
    r.z = fmaxf(rz + bc[o + 2], 0.f);
    r.w = fmaxf(rw + bc[o + 3], 0.f);
    *reinterpret_cast<float4*>(d_k2 + (size_t)m * 6144 + col) = r;
}

// ===================== stage 3: cls = g . k2^T + b_sp (split-K) =====================
__global__ void __launch_bounds__(256)
kernel_D(const float* __restrict__ g, const float* __restrict__ k2) {
    __shared__ __align__(16) float As[16][68];
    __shared__ __align__(16) float Bs[16][36];
    const int n0 = blockIdx.x * 32;
    const int ksplit = blockIdx.y;
    const int tid = threadIdx.x;
    const int tn = tid & 31;
    const int tg = tid >> 5;
    float acc[8];
#pragma unroll
    for (int j = 0; j < 8; j++) acc[j] = 0.f;
    const int kbase = ksplit * 192;
    for (int kc = 0; kc < 192; kc += 16) {
        const int k0 = kbase + kc;
        {
            int r = tid >> 2, kq = (tid & 3) * 4;
            float4 v = *reinterpret_cast<const float4*>(g + (size_t)r * 6144 + k0 + kq);
            As[kq + 0][r] = v.x; As[kq + 1][r] = v.y; As[kq + 2][r] = v.z; As[kq + 3][r] = v.w;
        }
        if (tid < 128) {
            int n = tid >> 2, kq = (tid & 3) * 4;
            int gn = n0 + n;
            float4 v = make_float4(0.f, 0.f, 0.f, 0.f);
            if (gn < 200) v = *reinterpret_cast<const float4*>(k2 + (size_t)gn * 6144 + k0 + kq);
            Bs[kq + 0][n] = v.x; Bs[kq + 1][n] = v.y; Bs[kq + 2][n] = v.z; Bs[kq + 3][n] = v.w;
        }
        __syncthreads();
#pragma unroll
        for (int k = 0; k < 16; k++) {
            float bv = Bs[k][tn];
            float a[8];
            *reinterpret_cast<float4*>(&a[0]) = *reinterpret_cast<const float4*>(&As[k][tg * 8]);
            *reinterpret_cast<float4*>(&a[4]) = *reinterpret_cast<const float4*>(&As[k][tg * 8 + 4]);
#pragma unroll
            for (int j = 0; j < 8; j++) acc[j] = fmaf(a[j], bv, acc[j]);
        }
        __syncthreads();
    }
    const int gn = n0 + tn;
    if (gn < 200) {
#pragma unroll
        for (int j = 0; j < 8; j++)
            d_part[((size_t)ksplit * 64 + tg * 8 + j) * 200 + gn] = acc[j];
    }
}

__global__ void reduce_D(const float* __restrict__ b_sp) {
    const int i = blockIdx.x * 256 + threadIdx.x;
    if (i < 12800) {
        float s = b_sp[0];
#pragma unroll
        for (int ks = 0; ks < 32; ks++) s += d_part[(size_t)ks * 12800 + i];
        d_cls[i] = s;
    }
}

// ===================== CosFace epilogue =====================
__global__ void norms_kernel(const float* __restrict__ wcls) {
    const int w = (blockIdx.x * blockDim.x + threadIdx.x) >> 5;
    const int lane = threadIdx.x & 31;
    if (w >= 264) return;
    const float* row = (w < 64) ? (d_cls + w * 200) : (wcls + (size_t)(w - 64) * 200);
    float s = 0.f;
    for (int t = lane; t < 200; t += 32) { float x = row[t]; s = fmaf(x, x, s); }
    s = wredsum(s);
    if (lane == 0) d_norms[w] = rsqrtf(s);
}

__global__ void cos_kernel(const float* __restrict__ wcls, const int* __restrict__ label,
                           float* __restrict__ out) {
    const int w = (blockIdx.x * blockDim.x + threadIdx.x) >> 5;
    const int lane = threadIdx.x & 31;
    if (w >= 12800) return;
    const int b = w / 200, c = w % 200;
    float s = 0.f;
    for (int t = lane; t < 200; t += 32)
        s = fmaf(d_cls[b * 200 + t], wcls[(size_t)c * 200 + t], s);
    s = wredsum(s);
    if (lane == 0) {
        float cosv = s * d_norms[b] * d_norms[64 + c];
        float m = (label[b] == c) ? 0.5f : 0.f;
        out[b * 200 + c] = 30.f * (cosv - m);
    }
}

// ===================== launch =====================
extern "C" void kernel_launch(void* const* d_in, const int* in_sizes, int n_in,
                              void* d_out, int out_size) {
    const float* feat     = (const float*)d_in[0];
    const int*   label    = (const int*)  d_in[1];
    const float* mem_feat = (const float*)d_in[2];
    const float* wt       = (const float*)d_in[3];
    const float* bt       = (const float*)d_in[4];
    const float* wc       = (const float*)d_in[5];
    const float* bc       = (const float*)d_in[6];
    const float* w_sp     = (const float*)d_in[7];
    const float* b_sp     = (const float*)d_in[8];
    const float* w_cls    = (const float*)d_in[9];
    float* out = (float*)d_out;

    cudaFuncSetAttribute(gemm_tap, cudaFuncAttributeMaxDynamicSharedMemorySize, SMEM_BYTES);

    __nv_bfloat16 *A1h, *A1l, *Bt1h, *Bt1l, *Bch, *Bcl, *k1h, *k1l;
    float *k2, *g;
    cudaGetSymbolAddress((void**)&A1h,  d_A1h);
    cudaGetSymbolAddress((void**)&A1l,  d_A1l);
    cudaGetSymbolAddress((void**)&Bt1h, d_Bt1h);
    cudaGetSymbolAddress((void**)&Bt1l, d_Bt1l);
    cudaGetSymbolAddress((void**)&Bch,  d_Bch);
    cudaGetSymbolAddress((void**)&Bcl,  d_Bcl);
    cudaGetSymbolAddress((void**)&k1h,  d_k1h);
    cudaGetSymbolAddress((void**)&k1l,  d_k1l);
    cudaGetSymbolAddress((void**)&k2,   d_k2);
    cudaGetSymbolAddress((void**)&g,    d_g);

    // operand prep (independent) + fused feat reduction
    prep_A1<<<2048, 256>>>(mem_feat);
    prep_Bt1<<<dim3(192, 64), 256>>>(wt);
    prep_Bc<<<16384, 256>>>(wc);
    g_kernel<<<16384, 256>>>(feat, w_sp);

    // stage 1: k1 = relu(A1 @ Bt1^T + bt), 96 tiles, 1 wave
    gemm_tap<<<dim3(48, 2), 256, SMEM_BYTES>>>(A1h, A1l, 2048, Bt1h, Bt1l, bt, 0);
    // stage 2: 224 uniform tap-GEMM units -> fp32 partials
    gemm_tap<<<dim3(112, 2), 256, SMEM_BYTES>>>(k1h, k1l, 6144, Bch, Bcl, bt, 1);
    // sum partials + bias + relu -> k2
    epi2<<<1200, 256>>>(bc);

    // stage 3 + CosFace
    kernel_D<<<dim3(7, 32), 256>>>(g, k2);
    reduce_D<<<50, 256>>>(b_sp);
    norms_kernel<<<33, 256>>>(w_cls);
    cos_kernel<<<1600, 256>>>(w_cls, label, out);

    (void)in_sizes; (void)n_in; (void)out_size;
}

// round 6
// speedup vs baseline: 2.4099x; 1.0049x over previous
#include <cuda_runtime.h>
#include <cuda_bf16.h>
#include <cstdint>

#define DI __device__ __forceinline__

// ===================== static scratch (no runtime alloc) =====================
__device__ __nv_bfloat16 d_A1h[256 * 2048];
__device__ __nv_bfloat16 d_A1l[256 * 2048];
__device__ __nv_bfloat16 d_Bt1h[6144u * 2048u];
__device__ __nv_bfloat16 d_Bt1l[6144u * 2048u];
__device__ __nv_bfloat16 d_Bch[3u * 2048u * 2048u];
__device__ __nv_bfloat16 d_Bcl[3u * 2048u * 2048u];
__device__ __nv_bfloat16 d_k1h[256 * 6144];
__device__ __nv_bfloat16 d_k1l[256 * 6144];
__device__ float d_p2[3u * 256u * 6144u];   // stage2 tap partials
__device__ float d_k2[256 * 6144];
__device__ float d_g[64 * 6144];
__device__ float d_part[32 * 64 * 200];
__device__ float d_cls[64 * 200];
__device__ float d_norms[264];

// ===================== PTX helpers =====================
DI uint32_t smem_u32(const void* p) {
    uint32_t a;
    asm("{ .reg .u64 t; cvta.to.shared.u64 t, %1; cvt.u32.u64 %0, t; }" : "=r"(a) : "l"(p));
    return a;
}
DI void cp16(uint32_t dst, const void* src) {
    asm volatile("cp.async.cg.shared.global [%0], [%1], 16;" :: "r"(dst), "l"(src) : "memory");
}
DI void cp_commit() { asm volatile("cp.async.commit_group;" ::: "memory"); }
DI void cp_wait1()  { asm volatile("cp.async.wait_group 1;" ::: "memory"); }
DI void cp_wait0()  { asm volatile("cp.async.wait_group 0;" ::: "memory"); }

DI void ldsm4(uint32_t* r, uint32_t addr) {
    asm volatile("ldmatrix.sync.aligned.m8n8.x4.shared.b16 {%0,%1,%2,%3}, [%4];"
        : "=r"(r[0]), "=r"(r[1]), "=r"(r[2]), "=r"(r[3]) : "r"(addr));
}

// m16n8k16 bf16 mma, fp32 accum
DI void mma_bf16(float* c, const uint32_t* a, uint32_t b0, uint32_t b1) {
    asm volatile(
        "mma.sync.aligned.m16n8k16.row.col.f32.bf16.bf16.f32 "
        "{%0,%1,%2,%3}, {%4,%5,%6,%7}, {%8,%9}, {%0,%1,%2,%3};"
        : "+f"(c[0]), "+f"(c[1]), "+f"(c[2]), "+f"(c[3])
        : "r"(a[0]), "r"(a[1]), "r"(a[2]), "r"(a[3]), "r"(b0), "r"(b1));
}

DI float wredsum(float v) {
#pragma unroll
    for (int o = 16; o > 0; o >>= 1) v += __shfl_xor_sync(0xffffffffu, v, o);
    return v;
}

// ===================== prep kernels =====================
__global__ void prep_A1(const float* __restrict__ mem_feat) {
    int idx = blockIdx.x * 256 + threadIdx.x;
    if (idx >= 256 * 2048) return;
    int row = idx >> 11;
    float x = (row < 200) ? mem_feat[(size_t)row * 2048 + (idx & 2047)] : 0.f;
    __nv_bfloat16 h = __float2bfloat16(x);
    d_A1h[idx] = h;
    d_A1l[idx] = __float2bfloat16(x - __bfloat162float(h));
}

// Bt1[m][i] = wt[i][(m&2047)*3 + (m>>11)]
__global__ void prep_Bt1(const float* __restrict__ wt) {
    __shared__ float s[32][97];
    const int m0 = blockIdx.x * 32;
    const int i0 = blockIdx.y * 32;
    const int p = m0 >> 11;
    const int o0 = m0 & 2047;
    const float* src = wt + (size_t)i0 * 6144 + (size_t)o0 * 3;
    for (int v = threadIdx.x; v < 768; v += 256) {
        int ii = v / 24, c4 = v % 24;
        float4 val = *reinterpret_cast<const float4*>(src + (size_t)ii * 6144 + c4 * 4);
        s[ii][c4 * 4 + 0] = val.x; s[ii][c4 * 4 + 1] = val.y;
        s[ii][c4 * 4 + 2] = val.z; s[ii][c4 * 4 + 3] = val.w;
    }
    __syncthreads();
    for (int v = threadIdx.x; v < 1024; v += 256) {
        int ml = v >> 5, il = v & 31;
        float x = s[il][ml * 3 + p];
        __nv_bfloat16 h = __float2bfloat16(x);
        size_t idx = (size_t)(m0 + ml) * 2048 + i0 + il;
        d_Bt1h[idx] = h;
        d_Bt1l[idx] = __float2bfloat16(x - __bfloat162float(h));
    }
}

// Bc[q][o][i] = wc[o][i*3+q]
__global__ void prep_Bc(const float* __restrict__ wc) {
    int idx = blockIdx.x * 256 + threadIdx.x;
    if (idx >= 2048 * 2048) return;
    int o = idx >> 11, i = idx & 2047;
    const float* r = wc + (size_t)o * 6144 + (size_t)i * 3;
#pragma unroll
    for (int q = 0; q < 3; q++) {
        float x = r[q];
        __nv_bfloat16 h = __float2bfloat16(x);
        size_t didx = (size_t)q * 4194304u + (size_t)idx;
        d_Bch[didx] = h;
        d_Bcl[didx] = __float2bfloat16(x - __bfloat162float(h));
    }
}

// g[b][q*2048+c] = sum_s w_sp[s]*feat[b,c,s+q-1]  (unrolled: 7 batched LDGs)
__global__ void g_kernel(const float* __restrict__ feat, const float* __restrict__ w_sp) {
    __shared__ float ws[200];
    const int tid = threadIdx.x;
    if (tid < 198) {
        float v = 0.f;
        if (tid >= 1 && tid <= 196) v = w_sp[tid - 1];
        ws[tid] = v;
    }
    __syncthreads();
    const int w = blockIdx.x * 8 + (tid >> 5);
    const int lane = tid & 31;
    const int b = w >> 11;
    const int c = w & 2047;
    const float* x = feat + ((size_t)b * 2048 + c) * 196;

    float xv[6];
#pragma unroll
    for (int k = 0; k < 6; k++) xv[k] = x[lane + 32 * k];
    float x6 = (lane < 4) ? x[192 + lane] : 0.f;

    float a0 = 0.f, a1 = 0.f, a2 = 0.f;
#pragma unroll
    for (int k = 0; k < 6; k++) {
        const int t = lane + 32 * k;
        a0 = fmaf(xv[k], ws[t + 2], a0);
        a1 = fmaf(xv[k], ws[t + 1], a1);
        a2 = fmaf(xv[k], ws[t],     a2);
    }
    if (lane < 4) {
        const int t = 192 + lane;
        a0 = fmaf(x6, ws[t + 2], a0);
        a1 = fmaf(x6, ws[t + 1], a1);
        a2 = fmaf(x6, ws[t],     a2);
    }
    a0 = wredsum(a0); a1 = wredsum(a1); a2 = wredsum(a2);
    if (lane == 0) {
        d_g[(size_t)b * 6144 + c]        = a0;
        d_g[(size_t)b * 6144 + 2048 + c] = a1;
        d_g[(size_t)b * 6144 + 4096 + c] = a2;
    }
}

// ===================== HMMA tap-GEMM: 128x128 tile, one K=2048 segment, 3-stage pipe =====================
static constexpr int SMEM_BYTES = 3 * 65536 + 1024;

DI uint32_t swz(int r, int g) {
    return ((uint32_t)r << 7) + (((uint32_t)(g ^ (r & 7))) << 4);
}

// mode 0 (stage1 tile): C = relu(A@B^T + bias) -> d_k1h/d_k1l (bf16 hi/lo)
// mode 1 (stage2 tap):  C = A@B^T raw fp32 -> d_p2[slot]
__global__ void __launch_bounds__(256, 1)
gemm_tap(const __nv_bfloat16* __restrict__ Ah, const __nv_bfloat16* __restrict__ Al, int lda,
         const __nv_bfloat16* __restrict__ Bh, const __nv_bfloat16* __restrict__ Bl,
         const float* __restrict__ bias, int mode)
{
    extern __shared__ char dsm[];
    __shared__ float sBias[128];

    const int tid = threadIdx.x;
    const int bx = blockIdx.x;
    const int m0 = blockIdx.y * 128;

    // unit geometry
    size_t aBase, bBase;
    int outcol, slot;
    if (mode == 0) {
        aBase = 0;
        bBase = (size_t)bx * 128u * 2048u;
        outcol = bx * 128;
        slot = 0;
    } else {
        const int tap = bx >> 4;
        const int ct = bx & 15;
        int p, s, j, q;
        if (tap < 2)      { p = 0; s = tap;     j = tap;   q = tap + 1; }
        else if (tap < 5) { p = 1; s = tap - 2; j = s;     q = s; }
        else              { p = 2; s = tap - 5; j = s + 1; q = s; }
        aBase = (size_t)j * 2048u;
        bBase = (size_t)q * 4194304u + (size_t)(ct * 128) * 2048u;
        outcol = p * 2048 + ct * 128;
        slot = s;
    }

    const uint32_t dsm_u = smem_u32(dsm);
    const uint32_t dbase = (dsm_u + 1023u) & ~1023u;

    if (mode == 0 && tid < 128) sBias[tid] = bias[(outcol & 2047) + tid];

    // loader geometry: 2 threads/row, 4 x 16B groups each, 4 operand regions
    const int lrow = tid >> 1;
    const int gset = (tid & 1) * 4;
    const size_t aRowB = (size_t)(m0 + lrow) * lda + aBase;
    const size_t bRowB = bBase + (size_t)lrow * 2048u;

    // compute geometry: 8 warps as 4(m) x 2(n)
    const int lane = tid & 31;
    const int warp = tid >> 5;
    const int m0w = (warp & 3) * 32;
    const int n0w = (warp >> 2) * 64;
    const int lr = lane & 15;
    const int kb = lane >> 4;

    float acc[2][8][4];
#pragma unroll
    for (int t = 0; t < 2; t++)
#pragma unroll
        for (int n = 0; n < 8; n++)
#pragma unroll
            for (int j = 0; j < 4; j++) acc[t][n][j] = 0.f;

#define LOADC(cc, bb) do { \
    const int _kc = (cc) << 6; \
    const uint32_t _b0 = dbase + (uint32_t)(bb) * 65536u; \
    const __nv_bfloat16* _ah = Ah + aRowB + _kc; \
    const __nv_bfloat16* _al = Al + aRowB + _kc; \
    const __nv_bfloat16* _bh = Bh + bRowB + _kc; \
    const __nv_bfloat16* _bl = Bl + bRowB + _kc; \
    _Pragma("unroll") \
    for (int _j = 0; _j < 4; _j++) { \
        const int _g = gset + _j; \
        const uint32_t _o = swz(lrow, _g); \
        cp16(_b0 + _o,           _ah + _g * 8); \
        cp16(_b0 + 16384u + _o,  _al + _g * 8); \
        cp16(_b0 + 32768u + _o,  _bh + _g * 8); \
        cp16(_b0 + 49152u + _o,  _bl + _g * 8); \
    } \
    cp_commit(); \
} while (0)

    LOADC(0, 0);
    LOADC(1, 1);

    for (int c = 0; c < 32; ++c) {
        if (c < 31) cp_wait1(); else cp_wait0();
        __syncthreads();
        if (c + 2 < 32) LOADC(c + 2, (c + 2) % 3);

        const uint32_t bb = dbase + (uint32_t)(c % 3) * 65536u;
        const uint32_t sAh = bb, sAl = bb + 16384u, sBh = bb + 32768u, sBl = bb + 49152u;

#pragma unroll
        for (int kk = 0; kk < 4; kk++) {
            const int gk = (kk << 1) | kb;

            // ---- load ALL fragments for this k-step first ----
            uint32_t ah[2][4], al[2][4], bhf[4][4], blf[4][4];
#pragma unroll
            for (int t = 0; t < 2; t++) {
                const uint32_t off = swz(m0w + t * 16 + lr, gk);
                ldsm4(ah[t], sAh + off);
                ldsm4(al[t], sAl + off);
            }
#pragma unroll
            for (int n = 0; n < 4; n++) {
                const uint32_t off = swz(n0w + n * 16 + lr, gk);
                ldsm4(bhf[n], sBh + off);
                ldsm4(blf[n], sBl + off);
            }

            // ---- product round 1: ah x bh (16 independent MMAs) ----
#pragma unroll
            for (int t = 0; t < 2; t++)
#pragma unroll
                for (int n = 0; n < 4; n++) {
                    mma_bf16(acc[t][2 * n],     ah[t], bhf[n][0], bhf[n][2]);
                    mma_bf16(acc[t][2 * n + 1], ah[t], bhf[n][1], bhf[n][3]);
                }
            // ---- product round 2: al x bh ----
#pragma unroll
            for (int t = 0; t < 2; t++)
#pragma unroll
                for (int n = 0; n < 4; n++) {
                    mma_bf16(acc[t][2 * n],     al[t], bhf[n][0], bhf[n][2]);
                    mma_bf16(acc[t][2 * n + 1], al[t], bhf[n][1], bhf[n][3]);
                }
            // ---- product round 3: ah x bl ----
#pragma unroll
            for (int t = 0; t < 2; t++)
#pragma unroll
                for (int n = 0; n < 4; n++) {
                    mma_bf16(acc[t][2 * n],     ah[t], blf[n][0], blf[n][2]);
                    mma_bf16(acc[t][2 * n + 1], ah[t], blf[n][1], blf[n][3]);
                }
        }
    }
#undef LOADC

    // ---- epilogue ----
    const int mrow = lane >> 2;
    const int npair = 2 * (lane & 3);
#pragma unroll
    for (int t = 0; t < 2; t++) {
#pragma unroll
        for (int nt = 0; nt < 8; nt++) {
            const int nloc = n0w + nt * 8 + npair;
            const int mA = m0 + m0w + t * 16 + mrow;
            if (mode == 0) {
                const float b0 = sBias[nloc], b1 = sBias[nloc + 1];
                const float v0 = fmaxf(acc[t][nt][0] + b0, 0.f);
                const float v1 = fmaxf(acc[t][nt][1] + b1, 0.f);
                const float v2 = fmaxf(acc[t][nt][2] + b0, 0.f);
                const float v3 = fmaxf(acc[t][nt][3] + b1, 0.f);
                const size_t i0 = (size_t)mA * 6144 + outcol + nloc;
                const size_t i1 = (size_t)(mA + 8) * 6144 + outcol + nloc;
                __nv_bfloat162 h0 = __floats2bfloat162_rn(v0, v1);
                __nv_bfloat162 h1 = __floats2bfloat162_rn(v2, v3);
                __nv_bfloat162 l0 = __floats2bfloat162_rn(v0 - __bfloat162float(h0.x),
                                                          v1 - __bfloat162float(h0.y));
                __nv_bfloat162 l1 = __floats2bfloat162_rn(v2 - __bfloat162float(h1.x),
                                                          v3 - __bfloat162float(h1.y));
                *reinterpret_cast<__nv_bfloat162*>(d_k1h + i0) = h0;
                *reinterpret_cast<__nv_bfloat162*>(d_k1h + i1) = h1;
                *reinterpret_cast<__nv_bfloat162*>(d_k1l + i0) = l0;
                *reinterpret_cast<__nv_bfloat162*>(d_k1l + i1) = l1;
            } else {
                const size_t base = (size_t)slot * 1572864u + (size_t)mA * 6144 + outcol + nloc;
                *reinterpret_cast<float2*>(d_p2 + base) =
                    make_float2(acc[t][nt][0], acc[t][nt][1]);
                *reinterpret_cast<float2*>(d_p2 + base + 8u * 6144u) =
                    make_float2(acc[t][nt][2], acc[t][nt][3]);
            }
        }
    }
}

// ===================== stage2 epilogue: k2 = relu(sum partials + bc) =====================
__global__ void epi2(const float* __restrict__ bc) {
    const int idx = blockIdx.x * 256 + threadIdx.x;   // over 200*1536 float4s
    if (idx >= 200 * 1536) return;
    const int m = idx / 1536;
    const int c4 = idx - m * 1536;
    const int col = c4 * 4;
    const int p = col >> 11;
    const int o = col & 2047;
    const float4* P = reinterpret_cast<const float4*>(d_p2);
    const size_t off = (size_t)m * 1536 + c4;
    float4 v0 = P[off];
    float4 v1 = P[393216u + off];
    float rx = v0.x + v1.x, ry = v0.y + v1.y, rz = v0.z + v1.z, rw = v0.w + v1.w;
    if (p == 1) {
        float4 v2 = P[786432u + off];
        rx += v2.x; ry += v2.y; rz += v2.z; rw += v2.w;
    }
    float4 r;
    r.x = fmaxf(rx + bc[o],     0.f);
    r.y = fmaxf(ry + bc[o + 1], 0.f);
    r.z = fmaxf(rz + bc[o + 2], 0.f);
    r.w = fmaxf(rw + bc[o + 3], 0.f);
    *reinterpret_cast<float4*>(d_k2 + (size_t)m * 6144 + col) = r;
}

// ===================== stage 3: cls = g . k2^T + b_sp (split-K) =====================
__global__ void __launch_bounds__(256)
kernel_D(const float* __restrict__ g, const float* __restrict__ k2) {
    __shared__ __align__(16) float As[16][68];
    __shared__ __align__(16) float Bs[16][36];
    const int n0 = blockIdx.x * 32;
    const int ksplit = blockIdx.y;
    const int tid = threadIdx.x;
    const int tn = tid & 31;
    const int tg = tid >> 5;
    float acc[8];
#pragma unroll
    for (int j = 0; j < 8; j++) acc[j] = 0.f;
    const int kbase = ksplit * 192;
    for (int kc = 0; kc < 192; kc += 16) {
        const int k0 = kbase + kc;
        {
            int r = tid >> 2, kq = (tid & 3) * 4;
            float4 v = *reinterpret_cast<const float4*>(g + (size_t)r * 6144 + k0 + kq);
            As[kq + 0][r] = v.x; As[kq + 1][r] = v.y; As[kq + 2][r] = v.z; As[kq + 3][r] = v.w;
        }
        if (tid < 128) {
            int n = tid >> 2, kq = (tid & 3) * 4;
            int gn = n0 + n;
            float4 v = make_float4(0.f, 0.f, 0.f, 0.f);
            if (gn < 200) v = *reinterpret_cast<const float4*>(k2 + (size_t)gn * 6144 + k0 + kq);
            Bs[kq + 0][n] = v.x; Bs[kq + 1][n] = v.y; Bs[kq + 2][n] = v.z; Bs[kq + 3][n] = v.w;
        }
        __syncthreads();
#pragma unroll
        for (int k = 0; k < 16; k++) {
            float bv = Bs[k][tn];
            float a[8];
            *reinterpret_cast<float4*>(&a[0]) = *reinterpret_cast<const float4*>(&As[k][tg * 8]);
            *reinterpret_cast<float4*>(&a[4]) = *reinterpret_cast<const float4*>(&As[k][tg * 8 + 4]);
#pragma unroll
            for (int j = 0; j < 8; j++) acc[j] = fmaf(a[j], bv, acc[j]);
        }
        __syncthreads();
    }
    const int gn = n0 + tn;
    if (gn < 200) {
#pragma unroll
        for (int j = 0; j < 8; j++)
            d_part[((size_t)ksplit * 64 + tg * 8 + j) * 200 + gn] = acc[j];
    }
}

__global__ void reduce_D(const float* __restrict__ b_sp) {
    const int i = blockIdx.x * 256 + threadIdx.x;
    if (i < 12800) {
        float s = b_sp[0];
#pragma unroll
        for (int ks = 0; ks < 32; ks++) s += d_part[(size_t)ks * 12800 + i];
        d_cls[i] = s;
    }
}

// ===================== CosFace epilogue =====================
__global__ void norms_kernel(const float* __restrict__ wcls) {
    const int w = (blockIdx.x * blockDim.x + threadIdx.x) >> 5;
    const int lane = threadIdx.x & 31;
    if (w >= 264) return;
    const float* row = (w < 64) ? (d_cls + w * 200) : (wcls + (size_t)(w - 64) * 200);
    float s = 0.f;
    for (int t = lane; t < 200; t += 32) { float x = row[t]; s = fmaf(x, x, s); }
    s = wredsum(s);
    if (lane == 0) d_norms[w] = rsqrtf(s);
}

__global__ void cos_kernel(const float* __restrict__ wcls, const int* __restrict__ label,
                           float* __restrict__ out) {
    const int w = (blockIdx.x * blockDim.x + threadIdx.x) >> 5;
    const int lane = threadIdx.x & 31;
    if (w >= 12800) return;
    const int b = w / 200, c = w % 200;
    float s = 0.f;
    for (int t = lane; t < 200; t += 32)
        s = fmaf(d_cls[b * 200 + t], wcls[(size_t)c * 200 + t], s);
    s = wredsum(s);
    if (lane == 0) {
        float cosv = s * d_norms[b] * d_norms[64 + c];
        float m = (label[b] == c) ? 0.5f : 0.f;
        out[b * 200 + c] = 30.f * (cosv - m);
    }
}

// ===================== launch =====================
extern "C" void kernel_launch(void* const* d_in, const int* in_sizes, int n_in,
                              void* d_out, int out_size) {
    const float* feat     = (const float*)d_in[0];
    const int*   label    = (const int*)  d_in[1];
    const float* mem_feat = (const float*)d_in[2];
    const float* wt       = (const float*)d_in[3];
    const float* bt       = (const float*)d_in[4];
    const float* wc       = (const float*)d_in[5];
    const float* bc       = (const float*)d_in[6];
    const float* w_sp     = (const float*)d_in[7];
    const float* b_sp     = (const float*)d_in[8];
    const float* w_cls    = (const float*)d_in[9];
    float* out = (float*)d_out;

    cudaFuncSetAttribute(gemm_tap, cudaFuncAttributeMaxDynamicSharedMemorySize, SMEM_BYTES);

    __nv_bfloat16 *A1h, *A1l, *Bt1h, *Bt1l, *Bch, *Bcl, *k1h, *k1l;
    float *k2, *g;
    cudaGetSymbolAddress((void**)&A1h,  d_A1h);
    cudaGetSymbolAddress((void**)&A1l,  d_A1l);
    cudaGetSymbolAddress((void**)&Bt1h, d_Bt1h);
    cudaGetSymbolAddress((void**)&Bt1l, d_Bt1l);
    cudaGetSymbolAddress((void**)&Bch,  d_Bch);
    cudaGetSymbolAddress((void**)&Bcl,  d_Bcl);
    cudaGetSymbolAddress((void**)&k1h,  d_k1h);
    cudaGetSymbolAddress((void**)&k1l,  d_k1l);
    cudaGetSymbolAddress((void**)&k2,   d_k2);
    cudaGetSymbolAddress((void**)&g,    d_g);

    // operand prep (independent) + fused feat reduction
    prep_A1<<<2048, 256>>>(mem_feat);
    prep_Bt1<<<dim3(192, 64), 256>>>(wt);
    prep_Bc<<<16384, 256>>>(wc);
    g_kernel<<<16384, 256>>>(feat, w_sp);

    // stage 1: k1 = relu(A1 @ Bt1^T + bt), 96 tiles, 1 wave
    gemm_tap<<<dim3(48, 2), 256, SMEM_BYTES>>>(A1h, A1l, 2048, Bt1h, Bt1l, bt, 0);
    // stage 2: 224 uniform tap-GEMM units -> fp32 partials
    gemm_tap<<<dim3(112, 2), 256, SMEM_BYTES>>>(k1h, k1l, 6144, Bch, Bcl, bt, 1);
    // sum partials + bias + relu -> k2
    epi2<<<1200, 256>>>(bc);

    // stage 3 + CosFace
    kernel_D<<<dim3(7, 32), 256>>>(g, k2);
    reduce_D<<<50, 256>>>(b_sp);
    norms_kernel<<<33, 256>>>(w_cls);
    cos_kernel<<<1600, 256>>>(w_cls, label, out);

    (void)in_sizes; (void)n_in; (void)out_size;
}